// round 16
// baseline (speedup 1.0000x reference)
#include <cuda_runtime.h>
#include <cuda_fp16.h>

#define NN 100000
#define EE 3200000
#define GG 512
#define HH 30
#define HP 32          // padded T row stride: 32 halves = 64B; A row: 32 floats = 128B
#define FIN 10

// ---- static scratch (zero-initialized at load; k_pool restores zeros each call) ----
__device__ __align__(128) __half d_T[NN * HP];  // h @ W, fp16 (64B rows)
__device__ __align__(128) float  d_A[NN * HP];  // aggregated output, fp32
__device__ float d_degf[NN];         // weighted degree MINUS self-loop (reset to 0)
__device__ float d_dis[NN];          // 1/sqrt(deg)
__device__ int   d_cnt[NN];          // in-degree count (reset to 0)
__device__ int   d_off[NN + 1];      // CSR offsets (by destination)
__device__ int   d_fill[NN];         // position-claim counters
__device__ int2  d_edge[EE];         // CSR slot: {src, float_bits(w*dis[src])}
__device__ float d_pooled[GG * HP];  // pooled features

// Count in-degree + weighted degree; 4 edges per thread (int4/float4 loads).
__global__ void k_cnt(const int* __restrict__ ei, const float* __restrict__ w) {
    int e4 = blockIdx.x * blockDim.x + threadIdx.x;
    if (e4 >= EE / 4) return;
    int4   c = reinterpret_cast<const int4*>(ei + EE)[e4];
    float4 v = reinterpret_cast<const float4*>(w)[e4];
    atomicAdd(&d_cnt[c.x], 1); atomicAdd(&d_degf[c.x], v.x);
    atomicAdd(&d_cnt[c.y], 1); atomicAdd(&d_degf[c.y], v.y);
    atomicAdd(&d_cnt[c.z], 1); atomicAdd(&d_degf[c.z], v.z);
    atomicAdd(&d_cnt[c.w], 1); atomicAdd(&d_degf[c.w], v.w);
}

// Single-block exclusive scan of d_cnt -> d_off / d_fill. 512 threads, chunk 196.
__global__ void k_scan() {
    __shared__ int s[512];
    const int CH = 196;                  // 512*196 = 100352 >= NN
    int t = threadIdx.x;
    int base = t * CH;
    int sum = 0;
    for (int k = 0; k < CH; k++) {
        int i = base + k;
        if (i < NN) sum += d_cnt[i];
    }
    s[t] = sum;
    __syncthreads();
    for (int off = 1; off < 512; off <<= 1) {
        int v = (t >= off) ? s[t - off] : 0;
        __syncthreads();
        s[t] += v;
        __syncthreads();
    }
    int run = s[t] - sum;                // exclusive prefix
    for (int k = 0; k < CH; k++) {
        int i = base + k;
        if (i < NN) {
            d_off[i] = run;
            d_fill[i] = run;
            run += d_cnt[i];
        }
    }
    if (t == 511) d_off[NN] = run;       // == EE
}

// Layer-1 matmul FUSED with dis computation (same index domain, independent).
// dis[i] = rsqrt(degf[i] + 1): +1 is the self-loop; degf reset-state is 0.
__global__ void k_mm1dis(const float* __restrict__ x, const float* __restrict__ W1) {
    __shared__ float sW[FIN * HH];
    for (int t = threadIdx.x; t < FIN * HH; t += blockDim.x) sW[t] = W1[t];
    __syncthreads();
    int i = blockIdx.x * blockDim.x + threadIdx.x;
    if (i >= NN) return;
    d_dis[i] = rsqrtf(d_degf[i] + 1.0f);
    float xv[FIN];
#pragma unroll
    for (int k = 0; k < FIN; k++) xv[k] = x[i * FIN + k];
#pragma unroll
    for (int j = 0; j < HH; j++) {
        float t = 0.0f;
#pragma unroll
        for (int k = 0; k < FIN; k++) t += xv[k] * sW[k * HH + j];
        d_T[i * HP + j] = __float2half_rn(t);
    }
    d_T[i * HP + 30] = __float2half_rn(0.0f);
    d_T[i * HP + 31] = __float2half_rn(0.0f);
}

// Scatter edges into CSR slots with fused coefficient {src, w*dis[src]}.
// 4 edges per thread (int4/float4 loads). Runs AFTER k_mm1dis (needs d_dis).
__global__ void k_build(const int* __restrict__ ei, const float* __restrict__ w) {
    int e4 = blockIdx.x * blockDim.x + threadIdx.x;
    if (e4 >= EE / 4) return;
    int4   r = reinterpret_cast<const int4*>(ei)[e4];
    int4   c = reinterpret_cast<const int4*>(ei + EE)[e4];
    float4 v = reinterpret_cast<const float4*>(w)[e4];
    int p;
    p = atomicAdd(&d_fill[c.x], 1); d_edge[p] = make_int2(r.x, __float_as_int(v.x * d_dis[r.x]));
    p = atomicAdd(&d_fill[c.y], 1); d_edge[p] = make_int2(r.y, __float_as_int(v.y * d_dis[r.y]));
    p = atomicAdd(&d_fill[c.z], 1); d_edge[p] = make_int2(r.z, __float_as_int(v.z * d_dis[r.z]));
    p = atomicAdd(&d_fill[c.w], 1); d_edge[p] = make_int2(r.w, __float_as_int(v.w * d_dis[r.w]));
}

// Layers 2/3: h = relu(A + b_prev); T = h @ W (fp16 store)
__global__ void k_mm23(const float* __restrict__ W, const float* __restrict__ bprev) {
    __shared__ float sW[HH * HH];
    __shared__ float sb[HH];
    for (int t = threadIdx.x; t < HH * HH; t += blockDim.x) sW[t] = W[t];
    if (threadIdx.x < HH) sb[threadIdx.x] = bprev[threadIdx.x];
    __syncthreads();
    int i = blockIdx.x * blockDim.x + threadIdx.x;
    if (i >= NN) return;
    float h[HH];
#pragma unroll
    for (int k = 0; k < HH; k++) h[k] = fmaxf(d_A[i * HP + k] + sb[k], 0.0f);
#pragma unroll
    for (int j = 0; j < HH; j++) {
        float t = 0.0f;
#pragma unroll
        for (int k = 0; k < HH; k++) t += h[k] * sW[k * HH + j];
        d_T[i * HP + j] = __float2half_rn(t);
    }
    d_T[i * HP + 30] = __float2half_rn(0.0f);
    d_T[i * HP + 31] = __float2half_rn(0.0f);
}

// Gather: TWO nodes per warp. lane = {half: which node, lp: feature PAIR}.
// Each lane accumulates 2 features (half2 row loads) in fp32, ILP2 on edges.
// A[i] = dis[i] * ( sum_j n_j*T[src_j] + dis[i]*T[i] ).
__global__ void k_gather() {
    int warp = (blockIdx.x * blockDim.x + threadIdx.x) >> 5;
    int lane = threadIdx.x & 31;
    int node = warp * 2 + (lane >> 4);   // NN even; all warps full
    int lp   = lane & 15;                // feature pair 0..15
    if (node >= NN) return;
    const __half2* T2 = reinterpret_cast<const __half2*>(d_T);
    int s = d_off[node], e = d_off[node + 1];
    float ax0 = 0.f, ay0 = 0.f, ax1 = 0.f, ay1 = 0.f;
    int j = s;
    for (; j + 1 < e; j += 2) {
        int2 m0 = d_edge[j];
        int2 m1 = d_edge[j + 1];
        __half2 h0 = T2[m0.x * 16 + lp];
        __half2 h1 = T2[m1.x * 16 + lp];
        float n0 = __int_as_float(m0.y);
        float n1 = __int_as_float(m1.y);
        ax0 += n0 * __low2float(h0);  ay0 += n0 * __high2float(h0);
        ax1 += n1 * __low2float(h1);  ay1 += n1 * __high2float(h1);
    }
    if (j < e) {
        int2 m = d_edge[j];
        __half2 h = T2[m.x * 16 + lp];
        float n = __int_as_float(m.y);
        ax0 += n * __low2float(h);  ay0 += n * __high2float(h);
    }
    float di = d_dis[node];
    __half2 hs = T2[node * 16 + lp];
    float2 o;
    o.x = di * ((ax0 + ax1) + di * __low2float(hs));
    o.y = di * ((ay0 + ay1) + di * __high2float(hs));
    reinterpret_cast<float2*>(d_A)[node * 16 + lp] = o;
}

// Pool + MLP + state reset, one block per graph (256 threads).
// Bounds via per-block binary search (batch sorted). Also zeroes d_cnt/d_degf
// for the NEXT call (reset-state == load-time state; every call identical work).
__global__ void k_pool(const int* __restrict__ batch, const float* __restrict__ b3,
                       const float* __restrict__ LW1, const float* __restrict__ Lb1,
                       const float* __restrict__ LW2, const float* __restrict__ Lb2,
                       float* __restrict__ out) {
    __shared__ float sm[8][32];
    __shared__ int sb2[2];               // lo, hi
    int g = blockIdx.x;
    int t = threadIdx.x;

    // reset counters for next replay (GG*256 = 131072 >= NN)
    int ri = g * blockDim.x + t;
    if (ri < NN) { d_cnt[ri] = 0; d_degf[ri] = 0.0f; }

    if (t < 2) {                          // lower_bound(g + t)
        int key = g + t;
        int lo = 0, hi = NN;
        while (lo < hi) {
            int mid = (lo + hi) >> 1;
            if (batch[mid] < key) lo = mid + 1; else hi = mid;
        }
        sb2[t] = lo;
    }
    __syncthreads();
    int lo = sb2[0], hi = sb2[1];

    int w = t >> 5, lane = t & 31;
    float bb = (lane < HH) ? b3[lane] : 0.0f;
    float mx = 0.0f;
    for (int i = lo + w; i < hi; i += 8)
        mx = fmaxf(mx, d_A[i * HP + lane] + bb);
    sm[w][lane] = mx;
    __syncthreads();
    if (t < 32) {
        float m = sm[0][lane];
#pragma unroll
        for (int ww = 1; ww < 8; ww++) m = fmaxf(m, sm[ww][lane]);
        d_pooled[g * HP + lane] = m;
    }
    __syncthreads();

    // MLP for this graph: thread 0..9 compute z, then threads 0,1 the outputs.
    __shared__ float z[10];
    if (t < 10) {
        float acc = Lb1[t];
#pragma unroll
        for (int k = 0; k < HH; k++) acc += d_pooled[g * HP + k] * LW1[k * 10 + t];
        z[t] = fmaxf(acc, 0.0f);
    }
    __syncthreads();
    if (t < 2) {
        float acc = Lb2[t];
#pragma unroll
        for (int j = 0; j < 10; j++) acc += z[j] * LW2[j * 2 + t];
        out[g * 2 + t] = acc;
    }
}

extern "C" void kernel_launch(void* const* d_in, const int* in_sizes, int n_in,
                              void* d_out, int out_size) {
    const float* x     = (const float*)d_in[0];
    const int*   ei    = (const int*)d_in[1];    // int32 (JAX x64 disabled)
    const int*   batch = (const int*)d_in[2];    // int32
    const float* w     = (const float*)d_in[3];
    const float* W1    = (const float*)d_in[4];
    const float* b1    = (const float*)d_in[5];
    const float* W2    = (const float*)d_in[6];
    const float* b2    = (const float*)d_in[7];
    const float* W3    = (const float*)d_in[8];
    const float* b3    = (const float*)d_in[9];
    const float* LW1   = (const float*)d_in[10];
    const float* Lb1   = (const float*)d_in[11];
    const float* LW2   = (const float*)d_in[12];
    const float* Lb2   = (const float*)d_in[13];
    float* out = (float*)d_out;

    const int TB = 256;
    const int gN  = (NN + TB - 1) / TB;
    const int gE4 = (EE / 4 + TB - 1) / TB;
    const int gW  = (NN / 2 * 32) / TB;   // two nodes per warp (exact multiple)

    k_cnt<<<gE4, TB>>>(ei, w);
    k_scan<<<1, 512>>>();
    k_mm1dis<<<gN, TB>>>(x, W1);          // also computes d_dis
    k_build<<<gE4, TB>>>(ei, w);

    k_gather<<<gW, TB>>>();

    k_mm23<<<gN, TB>>>(W2, b1);
    k_gather<<<gW, TB>>>();

    k_mm23<<<gN, TB>>>(W3, b2);
    k_gather<<<gW, TB>>>();

    k_pool<<<GG, TB>>>(batch, b3, LW1, Lb1, LW2, Lb2, out);
}

// round 17
// speedup vs baseline: 1.1841x; 1.1841x over previous
#include <cuda_runtime.h>
#include <cuda_fp16.h>

#define NN 100000
#define EE 3200000
#define GG 512
#define HH 30
#define HP 32          // padded T row stride: 32 halves = 64B; A row: 32 floats = 128B
#define FIN 10

// ---- static scratch (zero-initialized at load; k_pool restores zeros each call) ----
__device__ __align__(128) __half d_T[NN * HP];  // h @ W, fp16 (64B rows)
__device__ __align__(128) float  d_A[NN * HP];  // aggregated output, fp32
__device__ float d_degf[NN];         // weighted degree minus self-loop (reset to 0)
__device__ float d_dis[NN];          // 1/sqrt(deg)
__device__ int   d_cnt[NN];          // in-degree count (reset to 0)
__device__ int   d_off[NN + 1];      // CSR offsets (by destination)
__device__ int   d_fill[NN];         // position-claim counters
__device__ __align__(16) int2 d_edge[EE];  // CSR slot: {src, float_bits(w*dis[src])}
__device__ float d_pooled[GG * HP];  // pooled features

// Count in-degree + weighted degree. One edge per thread (R12 shape).
__global__ void k_cnt(const int* __restrict__ ei, const float* __restrict__ w) {
    int e = blockIdx.x * blockDim.x + threadIdx.x;
    if (e >= EE) return;
    int c = ei[EE + e];                  // destination
    atomicAdd(&d_cnt[c], 1);
    atomicAdd(&d_degf[c], w[e]);
}

// Single-block exclusive scan of d_cnt -> d_off / d_fill. 512 threads, chunk 196.
__global__ void k_scan() {
    __shared__ int s[512];
    const int CH = 196;                  // 512*196 = 100352 >= NN
    int t = threadIdx.x;
    int base = t * CH;
    int sum = 0;
    for (int k = 0; k < CH; k++) {
        int i = base + k;
        if (i < NN) sum += d_cnt[i];
    }
    s[t] = sum;
    __syncthreads();
    for (int off = 1; off < 512; off <<= 1) {
        int v = (t >= off) ? s[t - off] : 0;
        __syncthreads();
        s[t] += v;
        __syncthreads();
    }
    int run = s[t] - sum;                // exclusive prefix
    for (int k = 0; k < CH; k++) {
        int i = base + k;
        if (i < NN) {
            d_off[i] = run;
            d_fill[i] = run;
            run += d_cnt[i];
        }
    }
    if (t == 511) d_off[NN] = run;       // == EE
}

// Layer-1 matmul FUSED with dis computation (same index domain, independent).
// dis[i] = rsqrt(degf[i] + 1): +1 is the self-loop; degf reset-state is 0.
__global__ void k_mm1dis(const float* __restrict__ x, const float* __restrict__ W1) {
    __shared__ float sW[FIN * HH];
    for (int t = threadIdx.x; t < FIN * HH; t += blockDim.x) sW[t] = W1[t];
    __syncthreads();
    int i = blockIdx.x * blockDim.x + threadIdx.x;
    if (i >= NN) return;
    d_dis[i] = rsqrtf(d_degf[i] + 1.0f);
    float xv[FIN];
#pragma unroll
    for (int k = 0; k < FIN; k++) xv[k] = x[i * FIN + k];
#pragma unroll
    for (int j = 0; j < HH; j++) {
        float t = 0.0f;
#pragma unroll
        for (int k = 0; k < FIN; k++) t += xv[k] * sW[k * HH + j];
        d_T[i * HP + j] = __float2half_rn(t);
    }
    d_T[i * HP + 30] = __float2half_rn(0.0f);
    d_T[i * HP + 31] = __float2half_rn(0.0f);
}

// Scatter edges into CSR slots with fused coefficient {src, w*dis[src]}.
// One edge per thread (R12 shape). Runs AFTER k_mm1dis (needs d_dis).
__global__ void k_build(const int* __restrict__ ei, const float* __restrict__ w) {
    int e = blockIdx.x * blockDim.x + threadIdx.x;
    if (e >= EE) return;
    int r = ei[e];
    int c = ei[EE + e];
    float n = w[e] * d_dis[r];
    int pos = atomicAdd(&d_fill[c], 1);
    d_edge[pos] = make_int2(r, __float_as_int(n));
}

// Layers 2/3: h = relu(A + b_prev); T = h @ W (fp16 store)
__global__ void k_mm23(const float* __restrict__ W, const float* __restrict__ bprev) {
    __shared__ float sW[HH * HH];
    __shared__ float sb[HH];
    for (int t = threadIdx.x; t < HH * HH; t += blockDim.x) sW[t] = W[t];
    if (threadIdx.x < HH) sb[threadIdx.x] = bprev[threadIdx.x];
    __syncthreads();
    int i = blockIdx.x * blockDim.x + threadIdx.x;
    if (i >= NN) return;
    float h[HH];
#pragma unroll
    for (int k = 0; k < HH; k++) h[k] = fmaxf(d_A[i * HP + k] + sb[k], 0.0f);
#pragma unroll
    for (int j = 0; j < HH; j++) {
        float t = 0.0f;
#pragma unroll
        for (int k = 0; k < HH; k++) t += h[k] * sW[k * HH + j];
        d_T[i * HP + j] = __float2half_rn(t);
    }
    d_T[i * HP + 30] = __float2half_rn(0.0f);
    d_T[i * HP + 31] = __float2half_rn(0.0f);
}

// Gather: one warp per node, lane = feature column (R12 shape).
// NEW: edge meta loaded as int4 (2 edges per LDG.128, alignment peel) and
// T rows via __ldg. A[i] = dis[i]*( sum_j n_j*T[src_j] + dis[i]*T[i] ).
__global__ void k_gather() {
    int warp = (blockIdx.x * blockDim.x + threadIdx.x) >> 5;
    if (warp >= NN) return;
    int lane = threadIdx.x & 31;
    int s = d_off[warp], e = d_off[warp + 1];
    float a0 = 0.f, a1 = 0.f, a2 = 0.f, a3 = 0.f;
    int j = s;
    if ((j & 1) && j < e) {              // peel to 16B-aligned slot pair
        int2 m = d_edge[j];
        a0 += __int_as_float(m.y) * __half2float(__ldg(&d_T[m.x * HP + lane]));
        j++;
    }
    const int4* E4 = reinterpret_cast<const int4*>(d_edge);
    for (; j + 3 < e; j += 4) {
        int4 p = E4[j >> 1];             // edges j, j+1
        int4 q = E4[(j >> 1) + 1];       // edges j+2, j+3
        a0 += __int_as_float(p.y) * __half2float(__ldg(&d_T[p.x * HP + lane]));
        a1 += __int_as_float(p.w) * __half2float(__ldg(&d_T[p.z * HP + lane]));
        a2 += __int_as_float(q.y) * __half2float(__ldg(&d_T[q.x * HP + lane]));
        a3 += __int_as_float(q.w) * __half2float(__ldg(&d_T[q.z * HP + lane]));
    }
    for (; j < e; j++) {
        int2 m = d_edge[j];
        a0 += __int_as_float(m.y) * __half2float(__ldg(&d_T[m.x * HP + lane]));
    }
    float di = d_dis[warp];
    float self = __half2float(d_T[warp * HP + lane]);
    d_A[warp * HP + lane] = di * (((a0 + a1) + (a2 + a3)) + di * self);
}

// Pool + MLP + state reset, one block per graph (256 threads).
// Bounds via per-block binary search (batch sorted). Also zeroes d_cnt/d_degf
// for the NEXT call (reset-state == load-time state; identical work each call).
__global__ void k_pool(const int* __restrict__ batch, const float* __restrict__ b3,
                       const float* __restrict__ LW1, const float* __restrict__ Lb1,
                       const float* __restrict__ LW2, const float* __restrict__ Lb2,
                       float* __restrict__ out) {
    __shared__ float sm[8][32];
    __shared__ int sb2[2];               // lo, hi
    __shared__ float z[10];
    int g = blockIdx.x;
    int t = threadIdx.x;

    // reset counters for next replay (GG*256 = 131072 >= NN)
    int ri = g * blockDim.x + t;
    if (ri < NN) { d_cnt[ri] = 0; d_degf[ri] = 0.0f; }

    if (t < 2) {                         // lower_bound(g + t)
        int key = g + t;
        int lo = 0, hi = NN;
        while (lo < hi) {
            int mid = (lo + hi) >> 1;
            if (batch[mid] < key) lo = mid + 1; else hi = mid;
        }
        sb2[t] = lo;
    }
    __syncthreads();
    int lo = sb2[0], hi = sb2[1];

    int w = t >> 5, lane = t & 31;
    float bb = (lane < HH) ? b3[lane] : 0.0f;
    float mx = 0.0f;
    for (int i = lo + w; i < hi; i += 8)
        mx = fmaxf(mx, d_A[i * HP + lane] + bb);
    sm[w][lane] = mx;
    __syncthreads();
    if (t < 32) {
        float m = sm[0][lane];
#pragma unroll
        for (int ww = 1; ww < 8; ww++) m = fmaxf(m, sm[ww][lane]);
        d_pooled[g * HP + lane] = m;
    }
    __syncthreads();

    if (t < 10) {
        float acc = Lb1[t];
#pragma unroll
        for (int k = 0; k < HH; k++) acc += d_pooled[g * HP + k] * LW1[k * 10 + t];
        z[t] = fmaxf(acc, 0.0f);
    }
    __syncthreads();
    if (t < 2) {
        float acc = Lb2[t];
#pragma unroll
        for (int j = 0; j < 10; j++) acc += z[j] * LW2[j * 2 + t];
        out[g * 2 + t] = acc;
    }
}

extern "C" void kernel_launch(void* const* d_in, const int* in_sizes, int n_in,
                              void* d_out, int out_size) {
    const float* x     = (const float*)d_in[0];
    const int*   ei    = (const int*)d_in[1];    // int32 (JAX x64 disabled)
    const int*   batch = (const int*)d_in[2];    // int32
    const float* w     = (const float*)d_in[3];
    const float* W1    = (const float*)d_in[4];
    const float* b1    = (const float*)d_in[5];
    const float* W2    = (const float*)d_in[6];
    const float* b2    = (const float*)d_in[7];
    const float* W3    = (const float*)d_in[8];
    const float* b3    = (const float*)d_in[9];
    const float* LW1   = (const float*)d_in[10];
    const float* Lb1   = (const float*)d_in[11];
    const float* LW2   = (const float*)d_in[12];
    const float* Lb2   = (const float*)d_in[13];
    float* out = (float*)d_out;

    const int TB = 256;
    const int gN = (NN + TB - 1) / TB;
    const int gE = (EE + TB - 1) / TB;
    const int gW = (NN * 32) / TB;       // one warp per node (exact multiple)

    k_cnt<<<gE, TB>>>(ei, w);
    k_scan<<<1, 512>>>();
    k_mm1dis<<<gN, TB>>>(x, W1);         // also computes d_dis
    k_build<<<gE, TB>>>(ei, w);

    k_gather<<<gW, TB>>>();

    k_mm23<<<gN, TB>>>(W2, b1);
    k_gather<<<gW, TB>>>();

    k_mm23<<<gN, TB>>>(W3, b2);
    k_gather<<<gW, TB>>>();

    k_pool<<<GG, TB>>>(batch, b3, LW1, Lb1, LW2, Lb2, out);
}